// round 12
// baseline (speedup 1.0000x reference)
#include <cuda_runtime.h>
#include <cfloat>
#include <cstdint>

#define NNODE 20000
#define NEDGE 100000
#define DIM   256
#define HEADS 4
#define HC    (HEADS * DIM)   // 1024

// ---------------- scratch (static device globals; no allocation) -------------
__device__ float g_deg[NNODE];
__device__ float g_h  [(size_t)NNODE * DIM];
__device__ float g_x  [(size_t)NNODE * DIM];
__device__ float g_q  [(size_t)NNODE * HC];
__device__ float g_k  [(size_t)NNODE * HC];
__device__ float g_v  [(size_t)NNODE * HC];
__device__ float g_agg[(size_t)NNODE * DIM];   // head-averaged accumulator
__device__ float g_xr [(size_t)NNODE * DIM];
__device__ float g_tf [(size_t)NNODE * DIM];
__device__ float g_logits[(size_t)NEDGE * HEADS];
__device__ float g_m  [NNODE * HEADS];
__device__ float g_den[NNODE * HEADS];

// ---------------- helpers ----------------------------------------------------
__device__ __forceinline__ void atomicMaxF(float* addr, float v) {
    if (v >= 0.f) atomicMax((int*)addr, __float_as_int(v));
    else          atomicMin((unsigned int*)addr, __float_as_uint(v));
}

// Vectorized global reduction (sm_90+): one instruction, 4 floats, no return.
__device__ __forceinline__ void redAdd4(float* addr, float a, float b, float c, float d) {
    asm volatile("red.global.add.v4.f32 [%0], {%1,%2,%3,%4};"
                 :: "l"(addr), "f"(a), "f"(b), "f"(c), "f"(d) : "memory");
}

// ---------------- init: small fills (large clears via memsetAsync) -----------
__global__ void k_init(int nN) {
    size_t stride = (size_t)gridDim.x * blockDim.x;
    size_t i0 = (size_t)blockIdx.x * blockDim.x + threadIdx.x;
    size_t nh = (size_t)nN * HEADS;
    for (size_t i = i0; i < nh; i += stride) { g_den[i] = 0.f; g_m[i] = -FLT_MAX; }
    for (size_t i = i0; i < (size_t)nN; i += stride) g_deg[i] = 1.f;
}

// ---------------- GCN: degree ------------------------------------------------
__global__ void k_deg(const int* __restrict__ dst, int E) {
    int stride = gridDim.x * blockDim.x;
    for (int i = blockIdx.x * blockDim.x + threadIdx.x; i < E; i += stride)
        atomicAdd(&g_deg[dst[i]], 1.f);
}

// ---------------- GEMM core (device inline) ----------------------------------
// C[M,N] = A[M,K] * B + bias. Double-buffered smem, register prefetch.
// TRANSB: B is [N,K] row-major; else [K,N] row-major.
// BIAS_ROW: bias indexed by m instead of n. bias may be null.
template<bool TRANSB, bool BIAS_ROW>
__device__ __forceinline__ void gemm_body(
    const float* __restrict__ A, const float* __restrict__ B,
    const float* __restrict__ bias, float* __restrict__ C,
    int M, int N, int K,
    float As[2][8][128], float Bs[2][8][128])
{
    int tid   = threadIdx.x;
    int mBase = blockIdx.y * 128;
    int nBase = blockIdx.x * 128;
    int tx = tid & 15, ty = tid >> 4;

    int lr = tid >> 1;            // 0..127
    int lk = (tid & 1) * 4;       // 0 or 4
    int kr = tid >> 5;            // 0..7   (non-trans B)
    int cc = (tid & 31) * 4;      // 0..124 (non-trans B)

    float acc[8][8];
    #pragma unroll
    for (int i = 0; i < 8; i++)
        #pragma unroll
        for (int j = 0; j < 8; j++) acc[i][j] = 0.f;

    auto loadA = [&](int kt) -> float4 {
        int am = mBase + lr;
        if (am < M) return *(const float4*)(A + (size_t)am * K + kt + lk);
        return make_float4(0.f, 0.f, 0.f, 0.f);
    };
    auto loadB = [&](int kt) -> float4 {
        if (TRANSB) {
            int bn = nBase + lr;
            if (bn < N) return *(const float4*)(B + (size_t)bn * K + kt + lk);
            return make_float4(0.f, 0.f, 0.f, 0.f);
        } else {
            int bn = nBase + cc;
            if (bn < N) return *(const float4*)(B + (size_t)(kt + kr) * N + bn);
            return make_float4(0.f, 0.f, 0.f, 0.f);
        }
    };
    auto storeTiles = [&](int buf, float4 av, float4 bv) {
        As[buf][lk + 0][lr] = av.x; As[buf][lk + 1][lr] = av.y;
        As[buf][lk + 2][lr] = av.z; As[buf][lk + 3][lr] = av.w;
        if (TRANSB) {
            Bs[buf][lk + 0][lr] = bv.x; Bs[buf][lk + 1][lr] = bv.y;
            Bs[buf][lk + 2][lr] = bv.z; Bs[buf][lk + 3][lr] = bv.w;
        } else {
            *(float4*)&Bs[buf][kr][cc] = bv;
        }
    };

    {
        float4 av = loadA(0), bv = loadB(0);
        storeTiles(0, av, bv);
    }
    __syncthreads();

    int cur = 0;
    for (int kt = 0; kt < K; kt += 8) {
        float4 avn, bvn;
        bool more = (kt + 8) < K;
        if (more) { avn = loadA(kt + 8); bvn = loadB(kt + 8); }

        #pragma unroll
        for (int k = 0; k < 8; k++) {
            float a[8], b[8];
            *(float4*)(a)     = *(float4*)&As[cur][k][ty * 8];
            *(float4*)(a + 4) = *(float4*)&As[cur][k][ty * 8 + 4];
            *(float4*)(b)     = *(float4*)&Bs[cur][k][tx * 8];
            *(float4*)(b + 4) = *(float4*)&Bs[cur][k][tx * 8 + 4];
            #pragma unroll
            for (int i = 0; i < 8; i++)
                #pragma unroll
                for (int j = 0; j < 8; j++)
                    acc[i][j] += a[i] * b[j];
        }

        if (more) {
            storeTiles(cur ^ 1, avn, bvn);
            __syncthreads();
            cur ^= 1;
        }
    }

    #pragma unroll
    for (int i = 0; i < 8; i++) {
        int m = mBase + ty * 8 + i;
        if (m >= M) continue;
        float bm = (BIAS_ROW && bias) ? bias[m] : 0.f;
        #pragma unroll
        for (int jv = 0; jv < 2; jv++) {
            int n = nBase + tx * 8 + jv * 4;
            if (n >= N) continue;
            float4 o;
            o.x = acc[i][jv * 4 + 0]; o.y = acc[i][jv * 4 + 1];
            o.z = acc[i][jv * 4 + 2]; o.w = acc[i][jv * 4 + 3];
            if (BIAS_ROW) { o.x += bm; o.y += bm; o.z += bm; o.w += bm; }
            else if (bias) {
                o.x += bias[n]; o.y += bias[n + 1];
                o.z += bias[n + 2]; o.w += bias[n + 3];
            }
            *(float4*)(C + (size_t)m * N + n) = o;
        }
    }
}

template<bool TRANSB, bool BIAS_ROW>
__global__ __launch_bounds__(256, 2) void k_gemm(
    const float* __restrict__ A, const float* __restrict__ B,
    const float* __restrict__ bias, float* __restrict__ C,
    int M, int N, int K)
{
    __shared__ float As[2][8][128];
    __shared__ float Bs[2][8][128];
    gemm_body<TRANSB, BIAS_ROW>(A, B, bias, C, M, N, K, As, Bs);
}

// Fused Q/K/V/skip projection: blockIdx.z selects the weight/bias/output set.
// z=0..2: N=HC (8 col-tiles). z=3: skip, N=DIM (2 col-tiles; extra CTAs no-op).
struct ProjArgs {
    const float* W[4];
    const float* b[4];
    float*       O[4];
};

__global__ __launch_bounds__(256, 2) void k_gemm_proj(
    const float* __restrict__ A, ProjArgs args, int M, int K)
{
    __shared__ float As[2][8][128];
    __shared__ float Bs[2][8][128];
    int z = blockIdx.z;
    int n = (z == 3) ? DIM : HC;
    if (blockIdx.x * 128 >= n) return;           // no-op tail CTAs for skip
    gemm_body<false, false>(A, args.W[z], args.b[z], args.O[z], M, n, K, As, Bs);
}

// ---------------- GCN scatter (vectorized red.global) ------------------------
__global__ void k_gcn_scatter(const int* __restrict__ src, const int* __restrict__ dst, int E) {
    int lane = threadIdx.x & 31;
    int wstride = (gridDim.x * blockDim.x) >> 5;
    for (int e = (blockIdx.x * blockDim.x + threadIdx.x) >> 5; e < E; e += wstride) {
        int s = src[e], d = dst[e];
        float coef = rsqrtf(g_deg[s] * g_deg[d]);
        const float4* hp = (const float4*)(g_h + (size_t)s * DIM);
        float* xp = g_x + (size_t)d * DIM;
        #pragma unroll
        for (int it = 0; it < DIM / 128; it++) {
            int c = it * 128 + lane * 4;
            float4 hv = hp[c >> 2];
            redAdd4(xp + c, hv.x * coef, hv.y * coef, hv.z * coef, hv.w * coef);
        }
    }
}

// vectorized: one thread handles 4 consecutive channels of one node
__global__ void k_gcn_finish(const float* __restrict__ b_gcn, int nN) {
    int stride = gridDim.x * blockDim.x;
    int total = nN * (DIM / 4);
    for (int i = blockIdx.x * blockDim.x + threadIdx.x; i < total; i += stride) {
        int n  = i >> 6;                                 // /(DIM/4)
        int c4 = i & 63;                                 // float4 index within row
        float selfc = __fdividef(1.f, g_deg[n]);         // dinv^2 for the self loop
        float4 xv = ((const float4*)g_x)[i];
        float4 hv = ((const float4*)g_h)[i];
        float4 bv = ((const float4*)b_gcn)[c4];
        float4 o;
        o.x = fmaxf(xv.x + hv.x * selfc + bv.x, 0.f);
        o.y = fmaxf(xv.y + hv.y * selfc + bv.y, 0.f);
        o.z = fmaxf(xv.z + hv.z * selfc + bv.z, 0.f);
        o.w = fmaxf(xv.w + hv.w * selfc + bv.w, 0.f);
        ((float4*)g_x)[i] = o;
    }
}

// ---------------- attention: logits + segment max ----------------------------
__global__ void k_logits(const int* __restrict__ src, const int* __restrict__ dst, int E) {
    int lane = threadIdx.x & 31;
    int wstride = (gridDim.x * blockDim.x) >> 5;
    for (int e = (blockIdx.x * blockDim.x + threadIdx.x) >> 5; e < E; e += wstride) {
        int s = src[e], d = dst[e];
        const float4* qp = (const float4*)(g_q + (size_t)d * HC);
        const float4* kp = (const float4*)(g_k + (size_t)s * HC);
        #pragma unroll
        for (int h = 0; h < HEADS; h++) {
            int base = (h * DIM + lane * 8) >> 2;
            float4 a0 = qp[base], a1 = qp[base + 1];
            float4 b0 = kp[base], b1 = kp[base + 1];
            float sum = a0.x * b0.x + a0.y * b0.y + a0.z * b0.z + a0.w * b0.w
                      + a1.x * b1.x + a1.y * b1.y + a1.z * b1.z + a1.w * b1.w;
            #pragma unroll
            for (int o = 16; o > 0; o >>= 1) sum += __shfl_xor_sync(0xffffffffu, sum, o);
            if (lane == 0) {
                float l = sum * 0.0625f;   // / sqrt(256)
                g_logits[(size_t)e * HEADS + h] = l;
                atomicMaxF(&g_m[d * HEADS + h], l);
            }
        }
    }
}

// ---------------- attention: exp + segment sum (one thread per edge) ---------
__global__ void k_expden(const int* __restrict__ dst, int E) {
    int stride = gridDim.x * blockDim.x;
    for (int e = blockIdx.x * blockDim.x + threadIdx.x; e < E; e += stride) {
        int d = dst[e];
        float4 lg = *(const float4*)(g_logits + (size_t)e * HEADS);
        float4 mm = *(const float4*)(g_m + d * HEADS);
        float4 v;
        v.x = __expf(lg.x - mm.x); v.y = __expf(lg.y - mm.y);
        v.z = __expf(lg.z - mm.z); v.w = __expf(lg.w - mm.w);
        *(float4*)(g_logits + (size_t)e * HEADS) = v;
        redAdd4(&g_den[d * HEADS], v.x, v.y, v.z, v.w);
    }
}

// ---------------- attention: weighted scatter of V, head-avg fused -----------
// out[d, c] += 0.25 * sum_h alpha[e,h] * v[src, h, c]   (DIM-wide scatter)
__global__ void k_scatter_v(const int* __restrict__ src, const int* __restrict__ dst, int E) {
    int lane = threadIdx.x & 31;
    int wstride = (gridDim.x * blockDim.x) >> 5;
    for (int e = (blockIdx.x * blockDim.x + threadIdx.x) >> 5; e < E; e += wstride) {
        int s = src[e], d = dst[e];
        float4 lg = *(const float4*)(g_logits + (size_t)e * HEADS);
        float4 dn = *(const float4*)(g_den + d * HEADS);
        float al[HEADS];
        al[0] = 0.25f * lg.x / fmaxf(dn.x, 1e-16f);
        al[1] = 0.25f * lg.y / fmaxf(dn.y, 1e-16f);
        al[2] = 0.25f * lg.z / fmaxf(dn.z, 1e-16f);
        al[3] = 0.25f * lg.w / fmaxf(dn.w, 1e-16f);
        const float4* vp = (const float4*)(g_v + (size_t)s * HC);
        float* ap = g_agg + (size_t)d * DIM;
        #pragma unroll
        for (int it = 0; it < DIM / 128; it++) {
            int c = it * 128 + lane * 4;           // channel within DIM
            float4 acc = make_float4(0.f, 0.f, 0.f, 0.f);
            #pragma unroll
            for (int h = 0; h < HEADS; h++) {
                float4 vv = vp[(h * DIM + c) >> 2];
                float a = al[h];
                acc.x += vv.x * a; acc.y += vv.y * a;
                acc.z += vv.z * a; acc.w += vv.w * a;
            }
            redAdd4(ap + c, acc.x, acc.y, acc.z, acc.w);
        }
    }
}

// ---------------- beta gate + relu (agg already head-averaged) ---------------
__global__ __launch_bounds__(DIM) void k_node_final(const float* __restrict__ Wb, int nN) {
    for (int n = blockIdx.x; n < nN; n += gridDim.x) {
        int c = threadIdx.x;
        int lane = c & 31, wid = c >> 5;
        float o  = g_agg[(size_t)n * DIM + c];
        float xr = g_xr [(size_t)n * DIM + c];
        float p = o * Wb[c] + xr * Wb[DIM + c] + (o - xr) * Wb[2 * DIM + c];

        // warp reduce then cross-warp combine
        #pragma unroll
        for (int off = 16; off > 0; off >>= 1) p += __shfl_xor_sync(0xffffffffu, p, off);
        __shared__ float part[8];
        if (lane == 0) part[wid] = p;
        __syncthreads();
        float tot = part[0] + part[1] + part[2] + part[3]
                  + part[4] + part[5] + part[6] + part[7];
        float beta = 1.f / (1.f + __expf(-tot));
        g_tf[(size_t)n * DIM + c] = fmaxf(beta * xr + (1.f - beta) * o, 0.f);
        __syncthreads();
    }
}

// ---------------- launch -----------------------------------------------------
extern "C" void kernel_launch(void* const* d_in, const int* in_sizes, int n_in,
                              void* d_out, int out_size) {
    const float* f_all  = (const float*)d_in[0];
    const int*   ei     = (const int*)  d_in[1];
    const float* W_gcn  = (const float*)d_in[2];
    const float* b_gcn  = (const float*)d_in[3];
    const float* W_q    = (const float*)d_in[4];
    const float* b_q    = (const float*)d_in[5];
    const float* W_k    = (const float*)d_in[6];
    const float* b_k    = (const float*)d_in[7];
    const float* W_v    = (const float*)d_in[8];
    const float* b_v    = (const float*)d_in[9];
    const float* W_skip = (const float*)d_in[10];
    const float* b_skip = (const float*)d_in[11];
    const float* W_beta = (const float*)d_in[12];
    const float* W_cnn  = (const float*)d_in[13];
    const float* b_cnn  = (const float*)d_in[14];

    int N = in_sizes[0] / DIM;
    int E = in_sizes[1] / 2;
    const int* src = ei;
    const int* dst = ei + E;

    float *ph, *px, *pq, *pk, *pv, *pxr, *ptf, *pagg;
    cudaGetSymbolAddress((void**)&ph,   g_h);
    cudaGetSymbolAddress((void**)&px,   g_x);
    cudaGetSymbolAddress((void**)&pq,   g_q);
    cudaGetSymbolAddress((void**)&pk,   g_k);
    cudaGetSymbolAddress((void**)&pv,   g_v);
    cudaGetSymbolAddress((void**)&pxr,  g_xr);
    cudaGetSymbolAddress((void**)&ptf,  g_tf);
    cudaGetSymbolAddress((void**)&pagg, g_agg);

    int mTiles = (N + 127) / 128;

    // large accumulator clears at LTS-ceiling bandwidth; small fills in k_init
    cudaMemsetAsync(px,   0, (size_t)N * DIM * sizeof(float), 0);
    cudaMemsetAsync(pagg, 0, (size_t)N * DIM * sizeof(float), 0);
    k_init<<<160, 256>>>(N);
    k_deg<<<(E + 255) / 256, 256>>>(dst, E);

    // h = f_all @ W_gcn (no bias yet)
    k_gemm<false, false><<<dim3(DIM / 128, mTiles), 256>>>(f_all, W_gcn, nullptr, ph, N, DIM, DIM);
    k_gcn_scatter<<<(E + 7) / 8, 256>>>(src, dst, E);
    k_gcn_finish<<<(N * (DIM / 4) + 255) / 256, 256>>>(b_gcn, N);

    // Q, K, V, skip fused into one launch (grid.z selects the matrix)
    ProjArgs proj;
    proj.W[0] = W_q;    proj.W[1] = W_k;    proj.W[2] = W_v;    proj.W[3] = W_skip;
    proj.b[0] = b_q;    proj.b[1] = b_k;    proj.b[2] = b_v;    proj.b[3] = b_skip;
    proj.O[0] = pq;     proj.O[1] = pk;     proj.O[2] = pv;     proj.O[3] = pxr;
    k_gemm_proj<<<dim3(HC / 128, mTiles, 4), 256>>>(px, proj, N, DIM);

    // edge attention
    k_logits<<<(E + 7) / 8, 256>>>(src, dst, E);
    k_expden<<<(E + 255) / 256, 256>>>(dst, E);
    k_scatter_v<<<(E + 7) / 8, 256>>>(src, dst, E);

    // node epilogue
    k_node_final<<<N, DIM>>>(W_beta, N);

    // conv: out[c, n] = sum_d W_cnn[c,d] * tf[n,d] + b_cnn[c]; row-major [DIM, N] == d_out
    k_gemm<true, true><<<dim3(mTiles, DIM / 128), 256>>>(W_cnn, ptf, b_cnn, (float*)d_out, DIM, N, DIM);
}

// round 14
// speedup vs baseline: 1.4807x; 1.4807x over previous
#include <cuda_runtime.h>
#include <mma.h>
#include <cfloat>
#include <cstdint>

using namespace nvcuda;

#define NNODE 20000
#define NPAD  20096            // 157 * 128
#define NEDGE 100000
#define DIM   256
#define HEADS 4
#define HC    (HEADS * DIM)    // 1024

// 1x tf32 (fast, rel_err ~2-5e-4). Flip to true for 3xTF32 error compensation.
static constexpr bool TF32_SPLIT = false;

// ---------------- scratch (static device globals; no allocation) -------------
__device__ float g_deg[NNODE];
__device__ float g_h  [(size_t)NPAD * DIM];
__device__ float g_x  [(size_t)NPAD * DIM];
__device__ float g_q  [(size_t)NPAD * HC];
__device__ float g_k  [(size_t)NPAD * HC];
__device__ float g_v  [(size_t)NPAD * HC];
__device__ float g_agg[(size_t)NPAD * DIM];
__device__ float g_xr [(size_t)NPAD * DIM];
__device__ float g_tf [(size_t)NPAD * DIM];
__device__ float g_conv[(size_t)DIM * NPAD];
__device__ float g_logits[(size_t)NEDGE * HEADS];
__device__ float g_m  [NNODE * HEADS];
__device__ float g_den[NNODE * HEADS];

// ---------------- helpers ----------------------------------------------------
__device__ __forceinline__ void atomicMaxF(float* addr, float v) {
    if (v >= 0.f) atomicMax((int*)addr, __float_as_int(v));
    else          atomicMin((unsigned int*)addr, __float_as_uint(v));
}

__device__ __forceinline__ void redAdd4(float* addr, float a, float b, float c, float d) {
    asm volatile("red.global.add.v4.f32 [%0], {%1,%2,%3,%4};"
                 :: "l"(addr), "f"(a), "f"(b), "f"(c), "f"(d) : "memory");
}

// ---------------- init -------------------------------------------------------
__global__ void k_init(int nN) {
    size_t stride = (size_t)gridDim.x * blockDim.x;
    size_t i0 = (size_t)blockIdx.x * blockDim.x + threadIdx.x;
    size_t nh = (size_t)nN * HEADS;
    for (size_t i = i0; i < nh; i += stride) { g_den[i] = 0.f; g_m[i] = -FLT_MAX; }
    for (size_t i = i0; i < (size_t)nN; i += stride) g_deg[i] = 1.f;
}

__global__ void k_deg(const int* __restrict__ dst, int E) {
    int stride = gridDim.x * blockDim.x;
    for (int i = blockIdx.x * blockDim.x + threadIdx.x; i < E; i += stride)
        atomicAdd(&g_deg[dst[i]], 1.f);
}

// ---------------- TF32 wmma GEMM core ---------------------------------------
// C[M,N] = A[M,K] * B (+bias). Block tile 128x128, K-step 16, 8 warps.
// TRANSB: B is [N,K] row-major (rows must be padded/allocated to tile bound).
// Outputs C must be padded to the tile grid (rows and cols); only A row loads
// are bounds-guarded (A may be a harness buffer of exactly M rows).
template<bool TRANSB, bool BIAS_ROW, bool SPLIT>
__device__ __forceinline__ void wgemm_body(
    const float* __restrict__ A, const float* __restrict__ B,
    const float* __restrict__ bias, float* __restrict__ C,
    int M, int N, int K, int ldc,
    float As[2][128][20], float Bs[2][16][132], float stage[8][256])
{
    int tid = threadIdx.x;
    int wid = tid >> 5, lane = tid & 31;
    int mBase = blockIdx.y * 128, nBase = blockIdx.x * 128;
    int mw = (wid >> 2) * 64;     // warp tile: 64 rows x 32 cols
    int nw = (wid & 3) * 32;

    wmma::fragment<wmma::accumulator, 16, 16, 8, float> acc[4][2];
    #pragma unroll
    for (int i = 0; i < 4; i++)
        #pragma unroll
        for (int j = 0; j < 2; j++)
            wmma::fill_fragment(acc[i][j], 0.f);

    auto loadA = [&](int kt, int f) -> float4 {
        int row = mBase + (f >> 2);
        if (row < M) return *(const float4*)(A + (size_t)row * K + kt + (f & 3) * 4);
        return make_float4(0.f, 0.f, 0.f, 0.f);
    };
    auto loadB = [&](int kt, int f) -> float4 {
        if (TRANSB) {
            int n = nBase + (f >> 2);
            return *(const float4*)(B + (size_t)n * K + kt + (f & 3) * 4);
        } else {
            return *(const float4*)(B + (size_t)(kt + (f >> 5)) * N + nBase + (f & 31) * 4);
        }
    };
    auto storeT = [&](int buf, int f, float4 av, float4 bv) {
        *(float4*)&As[buf][f >> 2][(f & 3) * 4] = av;
        if (TRANSB) {
            int n = f >> 2, kq = (f & 3) * 4;
            Bs[buf][kq + 0][n] = bv.x;
            Bs[buf][kq + 1][n] = bv.y;
            Bs[buf][kq + 2][n] = bv.z;
            Bs[buf][kq + 3][n] = bv.w;
        } else {
            *(float4*)&Bs[buf][f >> 5][(f & 31) * 4] = bv;
        }
    };

    {
        float4 a0 = loadA(0, tid), a1 = loadA(0, tid + 256);
        float4 b0 = loadB(0, tid), b1 = loadB(0, tid + 256);
        storeT(0, tid, a0, b0);
        storeT(0, tid + 256, a1, b1);
    }
    __syncthreads();

    int cur = 0;
    for (int kt = 0; kt < K; kt += 16) {
        float4 a0, a1, b0, b1;
        bool more = (kt + 16) < K;
        if (more) {
            a0 = loadA(kt + 16, tid); a1 = loadA(kt + 16, tid + 256);
            b0 = loadB(kt + 16, tid); b1 = loadB(kt + 16, tid + 256);
        }

        #pragma unroll
        for (int k8 = 0; k8 < 16; k8 += 8) {
            wmma::fragment<wmma::matrix_b, 16, 16, 8, wmma::precision::tf32, wmma::row_major> bh[2], bl[2];
            #pragma unroll
            for (int j = 0; j < 2; j++) {
                wmma::load_matrix_sync(bh[j], &Bs[cur][k8][nw + j * 16], 132);
                #pragma unroll
                for (int t = 0; t < bh[j].num_elements; t++) {
                    float v = bh[j].x[t];
                    float hi = wmma::__float_to_tf32(v);
                    bh[j].x[t] = hi;
                    if (SPLIT) bl[j].x[t] = wmma::__float_to_tf32(v - hi);
                }
            }
            #pragma unroll
            for (int i = 0; i < 4; i++) {
                wmma::fragment<wmma::matrix_a, 16, 16, 8, wmma::precision::tf32, wmma::row_major> ah, alo;
                wmma::load_matrix_sync(ah, &As[cur][mw + i * 16][k8], 20);
                #pragma unroll
                for (int t = 0; t < ah.num_elements; t++) {
                    float v = ah.x[t];
                    float hi = wmma::__float_to_tf32(v);
                    ah.x[t] = hi;
                    if (SPLIT) alo.x[t] = wmma::__float_to_tf32(v - hi);
                }
                #pragma unroll
                for (int j = 0; j < 2; j++) {
                    wmma::mma_sync(acc[i][j], ah, bh[j], acc[i][j]);
                    if (SPLIT) {
                        wmma::mma_sync(acc[i][j], ah, bl[j], acc[i][j]);
                        wmma::mma_sync(acc[i][j], alo, bh[j], acc[i][j]);
                    }
                }
            }
        }

        if (more) {
            storeT(cur ^ 1, tid, a0, b0);
            storeT(cur ^ 1, tid + 256, a1, b1);
            __syncthreads();
            cur ^= 1;
        }
    }

    // epilogue: per-warp smem staging -> bias add -> coalesced float4 stores
    int r = lane >> 1, c0 = (lane & 1) * 8;
    #pragma unroll
    for (int i = 0; i < 4; i++)
        #pragma unroll
        for (int j = 0; j < 2; j++) {
            wmma::store_matrix_sync(stage[wid], acc[i][j], 16, wmma::mem_row_major);
            __syncwarp();
            int gm = mBase + mw + i * 16 + r;
            int gn = nBase + nw + j * 16 + c0;
            float4 v0 = *(float4*)&stage[wid][r * 16 + c0];
            float4 v1 = *(float4*)&stage[wid][r * 16 + c0 + 4];
            if (BIAS_ROW) {
                float bm = bias[gm];
                v0.x += bm; v0.y += bm; v0.z += bm; v0.w += bm;
                v1.x += bm; v1.y += bm; v1.z += bm; v1.w += bm;
            } else if (bias) {
                float4 bb0 = *(const float4*)(bias + gn);
                float4 bb1 = *(const float4*)(bias + gn + 4);
                v0.x += bb0.x; v0.y += bb0.y; v0.z += bb0.z; v0.w += bb0.w;
                v1.x += bb1.x; v1.y += bb1.y; v1.z += bb1.z; v1.w += bb1.w;
            }
            *(float4*)(C + (size_t)gm * ldc + gn)     = v0;
            *(float4*)(C + (size_t)gm * ldc + gn + 4) = v1;
            __syncwarp();
        }
}

template<bool TRANSB, bool BIAS_ROW, bool SPLIT>
__global__ __launch_bounds__(256) void k_wgemm(
    const float* __restrict__ A, const float* __restrict__ B,
    const float* __restrict__ bias, float* __restrict__ C,
    int M, int N, int K, int ldc)
{
    __shared__ float As[2][128][20];
    __shared__ float Bs[2][16][132];
    __shared__ float stage[8][256];
    wgemm_body<TRANSB, BIAS_ROW, SPLIT>(A, B, bias, C, M, N, K, ldc, As, Bs, stage);
}

// Fused Q/K/V/skip projection: blockIdx.z selects the weight/bias/output set.
struct ProjArgs {
    const float* W[4];
    const float* b[4];
    float*       O[4];
};

__global__ __launch_bounds__(256) void k_wgemm_proj(
    const float* __restrict__ A, ProjArgs args, int M, int K)
{
    __shared__ float As[2][128][20];
    __shared__ float Bs[2][16][132];
    __shared__ float stage[8][256];
    int z = blockIdx.z;
    int n = (z == 3) ? DIM : HC;
    if (blockIdx.x * 128 >= n) return;
    wgemm_body<false, false, TF32_SPLIT>(A, args.W[z], args.b[z], args.O[z], M, n, K, n, As, Bs, stage);
}

// ---------------- GCN scatter (vectorized red.global) ------------------------
__global__ void k_gcn_scatter(const int* __restrict__ src, const int* __restrict__ dst, int E) {
    int lane = threadIdx.x & 31;
    int wstride = (gridDim.x * blockDim.x) >> 5;
    for (int e = (blockIdx.x * blockDim.x + threadIdx.x) >> 5; e < E; e += wstride) {
        int s = src[e], d = dst[e];
        float coef = rsqrtf(g_deg[s] * g_deg[d]);
        const float4* hp = (const float4*)(g_h + (size_t)s * DIM);
        float* xp = g_x + (size_t)d * DIM;
        #pragma unroll
        for (int it = 0; it < DIM / 128; it++) {
            int c = it * 128 + lane * 4;
            float4 hv = hp[c >> 2];
            redAdd4(xp + c, hv.x * coef, hv.y * coef, hv.z * coef, hv.w * coef);
        }
    }
}

__global__ void k_gcn_finish(const float* __restrict__ b_gcn, int nN) {
    int stride = gridDim.x * blockDim.x;
    int total = nN * (DIM / 4);
    for (int i = blockIdx.x * blockDim.x + threadIdx.x; i < total; i += stride) {
        int n  = i >> 6;
        int c4 = i & 63;
        float selfc = __fdividef(1.f, g_deg[n]);
        float4 xv = ((const float4*)g_x)[i];
        float4 hv = ((const float4*)g_h)[i];
        float4 bv = ((const float4*)b_gcn)[c4];
        float4 o;
        o.x = fmaxf(xv.x + hv.x * selfc + bv.x, 0.f);
        o.y = fmaxf(xv.y + hv.y * selfc + bv.y, 0.f);
        o.z = fmaxf(xv.z + hv.z * selfc + bv.z, 0.f);
        o.w = fmaxf(xv.w + hv.w * selfc + bv.w, 0.f);
        ((float4*)g_x)[i] = o;
    }
}

// ---------------- attention: logits + segment max ----------------------------
__global__ void k_logits(const int* __restrict__ src, const int* __restrict__ dst, int E) {
    int lane = threadIdx.x & 31;
    int wstride = (gridDim.x * blockDim.x) >> 5;
    for (int e = (blockIdx.x * blockDim.x + threadIdx.x) >> 5; e < E; e += wstride) {
        int s = src[e], d = dst[e];
        const float4* qp = (const float4*)(g_q + (size_t)d * HC);
        const float4* kp = (const float4*)(g_k + (size_t)s * HC);
        #pragma unroll
        for (int h = 0; h < HEADS; h++) {
            int base = (h * DIM + lane * 8) >> 2;
            float4 a0 = qp[base], a1 = qp[base + 1];
            float4 b0 = kp[base], b1 = kp[base + 1];
            float sum = a0.x * b0.x + a0.y * b0.y + a0.z * b0.z + a0.w * b0.w
                      + a1.x * b1.x + a1.y * b1.y + a1.z * b1.z + a1.w * b1.w;
            #pragma unroll
            for (int o = 16; o > 0; o >>= 1) sum += __shfl_xor_sync(0xffffffffu, sum, o);
            if (lane == 0) {
                float l = sum * 0.0625f;
                g_logits[(size_t)e * HEADS + h] = l;
                atomicMaxF(&g_m[d * HEADS + h], l);
            }
        }
    }
}

__global__ void k_expden(const int* __restrict__ dst, int E) {
    int stride = gridDim.x * blockDim.x;
    for (int e = blockIdx.x * blockDim.x + threadIdx.x; e < E; e += stride) {
        int d = dst[e];
        float4 lg = *(const float4*)(g_logits + (size_t)e * HEADS);
        float4 mm = *(const float4*)(g_m + d * HEADS);
        float4 v;
        v.x = __expf(lg.x - mm.x); v.y = __expf(lg.y - mm.y);
        v.z = __expf(lg.z - mm.z); v.w = __expf(lg.w - mm.w);
        *(float4*)(g_logits + (size_t)e * HEADS) = v;
        redAdd4(&g_den[d * HEADS], v.x, v.y, v.z, v.w);
    }
}

__global__ void k_scatter_v(const int* __restrict__ src, const int* __restrict__ dst, int E) {
    int lane = threadIdx.x & 31;
    int wstride = (gridDim.x * blockDim.x) >> 5;
    for (int e = (blockIdx.x * blockDim.x + threadIdx.x) >> 5; e < E; e += wstride) {
        int s = src[e], d = dst[e];
        float4 lg = *(const float4*)(g_logits + (size_t)e * HEADS);
        float4 dn = *(const float4*)(g_den + d * HEADS);
        float al[HEADS];
        al[0] = 0.25f * lg.x / fmaxf(dn.x, 1e-16f);
        al[1] = 0.25f * lg.y / fmaxf(dn.y, 1e-16f);
        al[2] = 0.25f * lg.z / fmaxf(dn.z, 1e-16f);
        al[3] = 0.25f * lg.w / fmaxf(dn.w, 1e-16f);
        const float4* vp = (const float4*)(g_v + (size_t)s * HC);
        float* ap = g_agg + (size_t)d * DIM;
        #pragma unroll
        for (int it = 0; it < DIM / 128; it++) {
            int c = it * 128 + lane * 4;
            float4 acc = make_float4(0.f, 0.f, 0.f, 0.f);
            #pragma unroll
            for (int h = 0; h < HEADS; h++) {
                float4 vv = vp[(h * DIM + c) >> 2];
                float a = al[h];
                acc.x += vv.x * a; acc.y += vv.y * a;
                acc.z += vv.z * a; acc.w += vv.w * a;
            }
            redAdd4(ap + c, acc.x, acc.y, acc.z, acc.w);
        }
    }
}

// ---------------- beta gate + relu -------------------------------------------
__global__ __launch_bounds__(DIM) void k_node_final(const float* __restrict__ Wb, int nN) {
    for (int n = blockIdx.x; n < nN; n += gridDim.x) {
        int c = threadIdx.x;
        int lane = c & 31, wid = c >> 5;
        float o  = g_agg[(size_t)n * DIM + c];
        float xr = g_xr [(size_t)n * DIM + c];
        float p = o * Wb[c] + xr * Wb[DIM + c] + (o - xr) * Wb[2 * DIM + c];

        #pragma unroll
        for (int off = 16; off > 0; off >>= 1) p += __shfl_xor_sync(0xffffffffu, p, off);
        __shared__ float part[8];
        if (lane == 0) part[wid] = p;
        __syncthreads();
        float tot = part[0] + part[1] + part[2] + part[3]
                  + part[4] + part[5] + part[6] + part[7];
        float beta = 1.f / (1.f + __expf(-tot));
        g_tf[(size_t)n * DIM + c] = fmaxf(beta * xr + (1.f - beta) * o, 0.f);
        __syncthreads();
    }
}

// ---------------- final copy: padded conv scratch -> d_out -------------------
__global__ void k_copy_out(float* __restrict__ dst, int nN) {
    int stride = gridDim.x * blockDim.x;
    int perRow = nN / 4;                   // float4 per output row
    int total = DIM * perRow;
    const float4* srcv = (const float4*)g_conv;
    float4* dstv = (float4*)dst;
    for (int i = blockIdx.x * blockDim.x + threadIdx.x; i < total; i += stride) {
        int r = i / perRow, c = i - r * perRow;
        dstv[i] = srcv[(size_t)r * (NPAD / 4) + c];
    }
}

// ---------------- launch -----------------------------------------------------
extern "C" void kernel_launch(void* const* d_in, const int* in_sizes, int n_in,
                              void* d_out, int out_size) {
    const float* f_all  = (const float*)d_in[0];
    const int*   ei     = (const int*)  d_in[1];
    const float* W_gcn  = (const float*)d_in[2];
    const float* b_gcn  = (const float*)d_in[3];
    const float* W_q    = (const float*)d_in[4];
    const float* b_q    = (const float*)d_in[5];
    const float* W_k    = (const float*)d_in[6];
    const float* b_k    = (const float*)d_in[7];
    const float* W_v    = (const float*)d_in[8];
    const float* b_v    = (const float*)d_in[9];
    const float* W_skip = (const float*)d_in[10];
    const float* b_skip = (const float*)d_in[11];
    const float* W_beta = (const float*)d_in[12];
    const float* W_cnn  = (const float*)d_in[13];
    const float* b_cnn  = (const float*)d_in[14];

    int N = in_sizes[0] / DIM;
    int E = in_sizes[1] / 2;
    const int* src = ei;
    const int* dst = ei + E;

    float *ph, *px, *pq, *pk, *pv, *pxr, *ptf, *pagg, *pconv;
    cudaGetSymbolAddress((void**)&ph,    g_h);
    cudaGetSymbolAddress((void**)&px,    g_x);
    cudaGetSymbolAddress((void**)&pq,    g_q);
    cudaGetSymbolAddress((void**)&pk,    g_k);
    cudaGetSymbolAddress((void**)&pv,    g_v);
    cudaGetSymbolAddress((void**)&pxr,   g_xr);
    cudaGetSymbolAddress((void**)&ptf,   g_tf);
    cudaGetSymbolAddress((void**)&pagg,  g_agg);
    cudaGetSymbolAddress((void**)&pconv, g_conv);

    int mTiles = (N + 127) / 128;   // 157

    cudaMemsetAsync(px,   0, (size_t)N * DIM * sizeof(float), 0);
    cudaMemsetAsync(pagg, 0, (size_t)N * DIM * sizeof(float), 0);
    k_init<<<160, 256>>>(N);
    k_deg<<<(E + 255) / 256, 256>>>(dst, E);

    // h = f_all @ W_gcn (no bias)
    k_wgemm<false, false, TF32_SPLIT><<<dim3(DIM / 128, mTiles), 256>>>(
        f_all, W_gcn, nullptr, ph, N, DIM, DIM, DIM);
    k_gcn_scatter<<<(E + 7) / 8, 256>>>(src, dst, E);
    k_gcn_finish<<<(N * (DIM / 4) + 255) / 256, 256>>>(b_gcn, N);

    // Q, K, V, skip fused (grid.z selects matrix)
    ProjArgs proj;
    proj.W[0] = W_q;  proj.W[1] = W_k;  proj.W[2] = W_v;  proj.W[3] = W_skip;
    proj.b[0] = b_q;  proj.b[1] = b_k;  proj.b[2] = b_v;  proj.b[3] = b_skip;
    proj.O[0] = pq;   proj.O[1] = pk;   proj.O[2] = pv;   proj.O[3] = pxr;
    k_wgemm_proj<<<dim3(HC / 128, mTiles, 4), 256>>>(px, proj, N, DIM);

    // edge attention
    k_logits<<<(E + 7) / 8, 256>>>(src, dst, E);
    k_expden<<<(E + 255) / 256, 256>>>(dst, E);
    k_scatter_v<<<(E + 7) / 8, 256>>>(src, dst, E);

    // node epilogue
    k_node_final<<<N, DIM>>>(W_beta, N);

    // conv: g_conv[c, n] = sum_d W_cnn[c,d] * tf[n,d] + b_cnn[c]  (padded cols)
    k_wgemm<true, true, TF32_SPLIT><<<dim3(mTiles, DIM / 128), 256>>>(
        W_cnn, ptf, b_cnn, pconv, DIM, NPAD, DIM, NPAD);

    // compact padded scratch into d_out
    k_copy_out<<<(N * DIM / 4 + 255) / 256, 256>>>((float*)d_out, N);
}

// round 16
// speedup vs baseline: 1.5759x; 1.0643x over previous
#include <cuda_runtime.h>
#include <mma.h>
#include <cfloat>
#include <cstdint>

using namespace nvcuda;

#define NNODE 20000
#define NPAD  20096            // 157 * 128
#define NEDGE 100000
#define DIM   256
#define HEADS 4
#define HC    (HEADS * DIM)    // 1024

// ---------------- scratch (static device globals; no allocation) -------------
__device__ float g_deg[NNODE];
__device__ float g_h  [(size_t)NPAD * DIM];
__device__ float g_x  [(size_t)NPAD * DIM];
__device__ float g_q  [(size_t)NPAD * HC];
__device__ float g_k  [(size_t)NPAD * HC];
__device__ float g_v  [(size_t)NPAD * HC];
__device__ float g_agg[(size_t)NPAD * DIM];
__device__ float g_xr [(size_t)NPAD * DIM];
__device__ float g_tf [(size_t)NPAD * DIM];
__device__ float g_conv[(size_t)DIM * NPAD];
__device__ float g_logits[(size_t)NEDGE * HEADS];
__device__ float g_m  [NNODE * HEADS];
__device__ float g_den[NNODE * HEADS];

// ---------------- helpers ----------------------------------------------------
__device__ __forceinline__ void atomicMaxF(float* addr, float v) {
    if (v >= 0.f) atomicMax((int*)addr, __float_as_int(v));
    else          atomicMin((unsigned int*)addr, __float_as_uint(v));
}

__device__ __forceinline__ void redAdd4(float* addr, float a, float b, float c, float d) {
    asm volatile("red.global.add.v4.f32 [%0], {%1,%2,%3,%4};"
                 :: "l"(addr), "f"(a), "f"(b), "f"(c), "f"(d) : "memory");
}

__device__ __forceinline__ float4 tf32x4(float4 v) {
    v.x = wmma::__float_to_tf32(v.x);
    v.y = wmma::__float_to_tf32(v.y);
    v.z = wmma::__float_to_tf32(v.z);
    v.w = wmma::__float_to_tf32(v.w);
    return v;
}

// ---------------- init -------------------------------------------------------
__global__ void k_init(int nN) {
    size_t stride = (size_t)gridDim.x * blockDim.x;
    size_t i0 = (size_t)blockIdx.x * blockDim.x + threadIdx.x;
    size_t nh = (size_t)nN * HEADS;
    for (size_t i = i0; i < nh; i += stride) { g_den[i] = 0.f; g_m[i] = -FLT_MAX; }
    for (size_t i = i0; i < (size_t)nN; i += stride) g_deg[i] = 1.f;
}

__global__ void k_deg(const int* __restrict__ dst, int E) {
    int stride = gridDim.x * blockDim.x;
    for (int i = blockIdx.x * blockDim.x + threadIdx.x; i < E; i += stride)
        atomicAdd(&g_deg[dst[i]], 1.f);
}

// ---------------- TF32 wmma GEMM core ---------------------------------------
// C[M,N] = A[M,K] * B (+bias). Block tile 128x128, K-step 16, 8 warps.
// Inputs rounded to tf32 ONCE at smem-store time; fragments feed mma directly.
// TRANSB: B is [N,K] row-major (rows must be padded/allocated to tile bound).
// Outputs C must be padded to the tile grid; only A row loads are guarded.
template<bool TRANSB, bool BIAS_ROW>
__device__ __forceinline__ void wgemm_body(
    const float* __restrict__ A, const float* __restrict__ B,
    const float* __restrict__ bias, float* __restrict__ C,
    int M, int N, int K, int ldc,
    float As[2][128][20], float Bs[2][16][132], float stage[8][256])
{
    int tid = threadIdx.x;
    int wid = tid >> 5, lane = tid & 31;
    int mBase = blockIdx.y * 128, nBase = blockIdx.x * 128;
    int mw = (wid >> 2) * 64;     // warp tile: 64 rows x 32 cols
    int nw = (wid & 3) * 32;

    wmma::fragment<wmma::accumulator, 16, 16, 8, float> acc[4][2];
    #pragma unroll
    for (int i = 0; i < 4; i++)
        #pragma unroll
        for (int j = 0; j < 2; j++)
            wmma::fill_fragment(acc[i][j], 0.f);

    auto loadA = [&](int kt, int f) -> float4 {
        int row = mBase + (f >> 2);
        if (row < M) return *(const float4*)(A + (size_t)row * K + kt + (f & 3) * 4);
        return make_float4(0.f, 0.f, 0.f, 0.f);
    };
    auto loadB = [&](int kt, int f) -> float4 {
        if (TRANSB) {
            int n = nBase + (f >> 2);
            return *(const float4*)(B + (size_t)n * K + kt + (f & 3) * 4);
        } else {
            return *(const float4*)(B + (size_t)(kt + (f >> 5)) * N + nBase + (f & 31) * 4);
        }
    };
    // Rounds to tf32 as values enter smem: inner loop then has zero conversions.
    auto storeT = [&](int buf, int f, float4 av, float4 bv) {
        av = tf32x4(av);
        bv = tf32x4(bv);
        *(float4*)&As[buf][f >> 2][(f & 3) * 4] = av;
        if (TRANSB) {
            int n = f >> 2, kq = (f & 3) * 4;
            Bs[buf][kq + 0][n] = bv.x;
            Bs[buf][kq + 1][n] = bv.y;
            Bs[buf][kq + 2][n] = bv.z;
            Bs[buf][kq + 3][n] = bv.w;
        } else {
            *(float4*)&Bs[buf][f >> 5][(f & 31) * 4] = bv;
        }
    };

    {
        float4 a0 = loadA(0, tid), a1 = loadA(0, tid + 256);
        float4 b0 = loadB(0, tid), b1 = loadB(0, tid + 256);
        storeT(0, tid, a0, b0);
        storeT(0, tid + 256, a1, b1);
    }
    __syncthreads();

    int cur = 0;
    for (int kt = 0; kt < K; kt += 16) {
        float4 a0, a1, b0, b1;
        bool more = (kt + 16) < K;
        if (more) {
            a0 = loadA(kt + 16, tid); a1 = loadA(kt + 16, tid + 256);
            b0 = loadB(kt + 16, tid); b1 = loadB(kt + 16, tid + 256);
        }

        #pragma unroll
        for (int k8 = 0; k8 < 16; k8 += 8) {
            wmma::fragment<wmma::matrix_b, 16, 16, 8, wmma::precision::tf32, wmma::row_major> bf[2];
            #pragma unroll
            for (int j = 0; j < 2; j++)
                wmma::load_matrix_sync(bf[j], &Bs[cur][k8][nw + j * 16], 132);
            #pragma unroll
            for (int i = 0; i < 4; i++) {
                wmma::fragment<wmma::matrix_a, 16, 16, 8, wmma::precision::tf32, wmma::row_major> af;
                wmma::load_matrix_sync(af, &As[cur][mw + i * 16][k8], 20);
                #pragma unroll
                for (int j = 0; j < 2; j++)
                    wmma::mma_sync(acc[i][j], af, bf[j], acc[i][j]);
            }
        }

        if (more) {
            storeT(cur ^ 1, tid, a0, b0);
            storeT(cur ^ 1, tid + 256, a1, b1);
            __syncthreads();
            cur ^= 1;
        }
    }

    // epilogue: per-warp smem staging -> bias add -> coalesced float4 stores
    int r = lane >> 1, c0 = (lane & 1) * 8;
    #pragma unroll
    for (int i = 0; i < 4; i++)
        #pragma unroll
        for (int j = 0; j < 2; j++) {
            wmma::store_matrix_sync(stage[wid], acc[i][j], 16, wmma::mem_row_major);
            __syncwarp();
            int gm = mBase + mw + i * 16 + r;
            int gn = nBase + nw + j * 16 + c0;
            float4 v0 = *(float4*)&stage[wid][r * 16 + c0];
            float4 v1 = *(float4*)&stage[wid][r * 16 + c0 + 4];
            if (BIAS_ROW) {
                float bm = bias[gm];
                v0.x += bm; v0.y += bm; v0.z += bm; v0.w += bm;
                v1.x += bm; v1.y += bm; v1.z += bm; v1.w += bm;
            } else if (bias) {
                float4 bb0 = *(const float4*)(bias + gn);
                float4 bb1 = *(const float4*)(bias + gn + 4);
                v0.x += bb0.x; v0.y += bb0.y; v0.z += bb0.z; v0.w += bb0.w;
                v1.x += bb1.x; v1.y += bb1.y; v1.z += bb1.z; v1.w += bb1.w;
            }
            *(float4*)(C + (size_t)gm * ldc + gn)     = v0;
            *(float4*)(C + (size_t)gm * ldc + gn + 4) = v1;
            __syncwarp();
        }
}

template<bool TRANSB, bool BIAS_ROW>
__global__ __launch_bounds__(256) void k_wgemm(
    const float* __restrict__ A, const float* __restrict__ B,
    const float* __restrict__ bias, float* __restrict__ C,
    int M, int N, int K, int ldc)
{
    __shared__ float As[2][128][20];
    __shared__ float Bs[2][16][132];
    __shared__ float stage[8][256];
    wgemm_body<TRANSB, BIAS_ROW>(A, B, bias, C, M, N, K, ldc, As, Bs, stage);
}

// Fused Q/K/V/skip projection: blockIdx.z selects the weight/bias/output set.
struct ProjArgs {
    const float* W[4];
    const float* b[4];
    float*       O[4];
};

__global__ __launch_bounds__(256) void k_wgemm_proj(
    const float* __restrict__ A, ProjArgs args, int M, int K)
{
    __shared__ float As[2][128][20];
    __shared__ float Bs[2][16][132];
    __shared__ float stage[8][256];
    int z = blockIdx.z;
    int n = (z == 3) ? DIM : HC;
    if (blockIdx.x * 128 >= n) return;
    wgemm_body<false, false>(A, args.W[z], args.b[z], args.O[z], M, n, K, n, As, Bs, stage);
}

// ---------------- GCN scatter (vectorized red.global) ------------------------
__global__ void k_gcn_scatter(const int* __restrict__ src, const int* __restrict__ dst, int E) {
    int lane = threadIdx.x & 31;
    int wstride = (gridDim.x * blockDim.x) >> 5;
    for (int e = (blockIdx.x * blockDim.x + threadIdx.x) >> 5; e < E; e += wstride) {
        int s = src[e], d = dst[e];
        float coef = rsqrtf(g_deg[s] * g_deg[d]);
        const float4* hp = (const float4*)(g_h + (size_t)s * DIM);
        float* xp = g_x + (size_t)d * DIM;
        #pragma unroll
        for (int it = 0; it < DIM / 128; it++) {
            int c = it * 128 + lane * 4;
            float4 hv = hp[c >> 2];
            redAdd4(xp + c, hv.x * coef, hv.y * coef, hv.z * coef, hv.w * coef);
        }
    }
}

__global__ void k_gcn_finish(const float* __restrict__ b_gcn, int nN) {
    int stride = gridDim.x * blockDim.x;
    int total = nN * (DIM / 4);
    for (int i = blockIdx.x * blockDim.x + threadIdx.x; i < total; i += stride) {
        int n  = i >> 6;
        int c4 = i & 63;
        float selfc = __fdividef(1.f, g_deg[n]);
        float4 xv = ((const float4*)g_x)[i];
        float4 hv = ((const float4*)g_h)[i];
        float4 bv = ((const float4*)b_gcn)[c4];
        float4 o;
        o.x = fmaxf(xv.x + hv.x * selfc + bv.x, 0.f);
        o.y = fmaxf(xv.y + hv.y * selfc + bv.y, 0.f);
        o.z = fmaxf(xv.z + hv.z * selfc + bv.z, 0.f);
        o.w = fmaxf(xv.w + hv.w * selfc + bv.w, 0.f);
        ((float4*)g_x)[i] = o;
    }
}

// ---------------- attention: logits + segment max ----------------------------
__global__ void k_logits(const int* __restrict__ src, const int* __restrict__ dst, int E) {
    int lane = threadIdx.x & 31;
    int wstride = (gridDim.x * blockDim.x) >> 5;
    for (int e = (blockIdx.x * blockDim.x + threadIdx.x) >> 5; e < E; e += wstride) {
        int s = src[e], d = dst[e];
        const float4* qp = (const float4*)(g_q + (size_t)d * HC);
        const float4* kp = (const float4*)(g_k + (size_t)s * HC);
        #pragma unroll
        for (int h = 0; h < HEADS; h++) {
            int base = (h * DIM + lane * 8) >> 2;
            float4 a0 = qp[base], a1 = qp[base + 1];
            float4 b0 = kp[base], b1 = kp[base + 1];
            float sum = a0.x * b0.x + a0.y * b0.y + a0.z * b0.z + a0.w * b0.w
                      + a1.x * b1.x + a1.y * b1.y + a1.z * b1.z + a1.w * b1.w;
            #pragma unroll
            for (int o = 16; o > 0; o >>= 1) sum += __shfl_xor_sync(0xffffffffu, sum, o);
            if (lane == 0) {
                float l = sum * 0.0625f;
                g_logits[(size_t)e * HEADS + h] = l;
                atomicMaxF(&g_m[d * HEADS + h], l);
            }
        }
    }
}

__global__ void k_expden(const int* __restrict__ dst, int E) {
    int stride = gridDim.x * blockDim.x;
    for (int e = blockIdx.x * blockDim.x + threadIdx.x; e < E; e += stride) {
        int d = dst[e];
        float4 lg = *(const float4*)(g_logits + (size_t)e * HEADS);
        float4 mm = *(const float4*)(g_m + d * HEADS);
        float4 v;
        v.x = __expf(lg.x - mm.x); v.y = __expf(lg.y - mm.y);
        v.z = __expf(lg.z - mm.z); v.w = __expf(lg.w - mm.w);
        *(float4*)(g_logits + (size_t)e * HEADS) = v;
        redAdd4(&g_den[d * HEADS], v.x, v.y, v.z, v.w);
    }
}

__global__ void k_scatter_v(const int* __restrict__ src, const int* __restrict__ dst, int E) {
    int lane = threadIdx.x & 31;
    int wstride = (gridDim.x * blockDim.x) >> 5;
    for (int e = (blockIdx.x * blockDim.x + threadIdx.x) >> 5; e < E; e += wstride) {
        int s = src[e], d = dst[e];
        float4 lg = *(const float4*)(g_logits + (size_t)e * HEADS);
        float4 dn = *(const float4*)(g_den + d * HEADS);
        float al[HEADS];
        al[0] = 0.25f * lg.x / fmaxf(dn.x, 1e-16f);
        al[1] = 0.25f * lg.y / fmaxf(dn.y, 1e-16f);
        al[2] = 0.25f * lg.z / fmaxf(dn.z, 1e-16f);
        al[3] = 0.25f * lg.w / fmaxf(dn.w, 1e-16f);
        const float4* vp = (const float4*)(g_v + (size_t)s * HC);
        float* ap = g_agg + (size_t)d * DIM;
        #pragma unroll
        for (int it = 0; it < DIM / 128; it++) {
            int c = it * 128 + lane * 4;
            float4 acc = make_float4(0.f, 0.f, 0.f, 0.f);
            #pragma unroll
            for (int h = 0; h < HEADS; h++) {
                float4 vv = vp[(h * DIM + c) >> 2];
                float a = al[h];
                acc.x += vv.x * a; acc.y += vv.y * a;
                acc.z += vv.z * a; acc.w += vv.w * a;
            }
            redAdd4(ap + c, acc.x, acc.y, acc.z, acc.w);
        }
    }
}

// ---------------- beta gate + relu -------------------------------------------
__global__ __launch_bounds__(DIM) void k_node_final(const float* __restrict__ Wb, int nN) {
    for (int n = blockIdx.x; n < nN; n += gridDim.x) {
        int c = threadIdx.x;
        int lane = c & 31, wid = c >> 5;
        float o  = g_agg[(size_t)n * DIM + c];
        float xr = g_xr [(size_t)n * DIM + c];
        float p = o * Wb[c] + xr * Wb[DIM + c] + (o - xr) * Wb[2 * DIM + c];

        #pragma unroll
        for (int off = 16; off > 0; off >>= 1) p += __shfl_xor_sync(0xffffffffu, p, off);
        __shared__ float part[8];
        if (lane == 0) part[wid] = p;
        __syncthreads();
        float tot = part[0] + part[1] + part[2] + part[3]
                  + part[4] + part[5] + part[6] + part[7];
        float beta = 1.f / (1.f + __expf(-tot));
        g_tf[(size_t)n * DIM + c] = fmaxf(beta * xr + (1.f - beta) * o, 0.f);
        __syncthreads();
    }
}

// ---------------- final copy: padded conv scratch -> d_out -------------------
__global__ void k_copy_out(float* __restrict__ dst, int nN) {
    int stride = gridDim.x * blockDim.x;
    int perRow = nN / 4;                   // float4 per output row
    int total = DIM * perRow;
    const float4* srcv = (const float4*)g_conv;
    float4* dstv = (float4*)dst;
    for (int i = blockIdx.x * blockDim.x + threadIdx.x; i < total; i += stride) {
        int r = i / perRow, c = i - r * perRow;
        dstv[i] = srcv[(size_t)r * (NPAD / 4) + c];
    }
}

// ---------------- launch -----------------------------------------------------
extern "C" void kernel_launch(void* const* d_in, const int* in_sizes, int n_in,
                              void* d_out, int out_size) {
    const float* f_all  = (const float*)d_in[0];
    const int*   ei     = (const int*)  d_in[1];
    const float* W_gcn  = (const float*)d_in[2];
    const float* b_gcn  = (const float*)d_in[3];
    const float* W_q    = (const float*)d_in[4];
    const float* b_q    = (const float*)d_in[5];
    const float* W_k    = (const float*)d_in[6];
    const float* b_k    = (const float*)d_in[7];
    const float* W_v    = (const float*)d_in[8];
    const float* b_v    = (const float*)d_in[9];
    const float* W_skip = (const float*)d_in[10];
    const float* b_skip = (const float*)d_in[11];
    const float* W_beta = (const float*)d_in[12];
    const float* W_cnn  = (const float*)d_in[13];
    const float* b_cnn  = (const float*)d_in[14];

    int N = in_sizes[0] / DIM;
    int E = in_sizes[1] / 2;
    const int* src = ei;
    const int* dst = ei + E;

    float *ph, *px, *pq, *pk, *pv, *pxr, *ptf, *pagg, *pconv;
    cudaGetSymbolAddress((void**)&ph,    g_h);
    cudaGetSymbolAddress((void**)&px,    g_x);
    cudaGetSymbolAddress((void**)&pq,    g_q);
    cudaGetSymbolAddress((void**)&pk,    g_k);
    cudaGetSymbolAddress((void**)&pv,    g_v);
    cudaGetSymbolAddress((void**)&pxr,   g_xr);
    cudaGetSymbolAddress((void**)&ptf,   g_tf);
    cudaGetSymbolAddress((void**)&pagg,  g_agg);
    cudaGetSymbolAddress((void**)&pconv, g_conv);

    int mTiles = (N + 127) / 128;   // 157

    cudaMemsetAsync(px,   0, (size_t)N * DIM * sizeof(float), 0);
    cudaMemsetAsync(pagg, 0, (size_t)N * DIM * sizeof(float), 0);
    k_init<<<160, 256>>>(N);
    k_deg<<<(E + 255) / 256, 256>>>(dst, E);

    // h = f_all @ W_gcn (no bias)
    k_wgemm<false, false><<<dim3(DIM / 128, mTiles), 256>>>(
        f_all, W_gcn, nullptr, ph, N, DIM, DIM, DIM);
    k_gcn_scatter<<<(E + 7) / 8, 256>>>(src, dst, E);
    k_gcn_finish<<<(N * (DIM / 4) + 255) / 256, 256>>>(b_gcn, N);

    // Q, K, V, skip fused (grid.z selects matrix)
    ProjArgs proj;
    proj.W[0] = W_q;  proj.W[1] = W_k;  proj.W[2] = W_v;  proj.W[3] = W_skip;
    proj.b[0] = b_q;  proj.b[1] = b_k;  proj.b[2] = b_v;  proj.b[3] = b_skip;
    proj.O[0] = pq;   proj.O[1] = pk;   proj.O[2] = pv;   proj.O[3] = pxr;
    k_wgemm_proj<<<dim3(HC / 128, mTiles, 4), 256>>>(px, proj, N, DIM);

    // edge attention
    k_logits<<<(E + 7) / 8, 256>>>(src, dst, E);
    k_expden<<<(E + 255) / 256, 256>>>(dst, E);
    k_scatter_v<<<(E + 7) / 8, 256>>>(src, dst, E);

    // node epilogue
    k_node_final<<<N, DIM>>>(W_beta, N);

    // conv: g_conv[c, n] = sum_d W_cnn[c,d] * tf[n,d] + b_cnn[c]  (padded cols)
    k_wgemm<true, true><<<dim3(mTiles, DIM / 128), 256>>>(
        W_cnn, ptf, b_cnn, pconv, DIM, NPAD, DIM, NPAD);

    // compact padded scratch into d_out
    k_copy_out<<<(N * DIM / 4 + 255) / 256, 256>>>((float*)d_out, N);
}